// round 9
// baseline (speedup 1.0000x reference)
#include <cuda_runtime.h>
#include <cuda_bf16.h>

// ---------------- device scratch (static) ----------------
__device__ float g_uw[256];          // u/w projection vectors
__device__ unsigned g_bm[400 * 16];  // gso bitmap [i][word]

// ---------------- helpers ----------------
__device__ __forceinline__ unsigned bf2pack(float hi, float lo) {
  unsigned r;
  asm("cvt.rn.bf16x2.f32 %0, %1, %2;" : "=r"(r) : "f"(hi), "f"(lo));
  return r;
}
__device__ __forceinline__ float up_hi(unsigned r) { return __uint_as_float(r & 0xFFFF0000u); }
__device__ __forceinline__ float up_lo(unsigned r) { return __uint_as_float(r << 16); }

__device__ __forceinline__ void mma16816(float* c, const unsigned* a, unsigned b0, unsigned b1) {
  asm volatile(
      "mma.sync.aligned.m16n8k16.row.col.f32.bf16.bf16.f32 "
      "{%0,%1,%2,%3}, {%4,%5,%6,%7}, {%8,%9}, {%0,%1,%2,%3};"
      : "+f"(c[0]), "+f"(c[1]), "+f"(c[2]), "+f"(c[3])
      : "r"(a[0]), "r"(a[1]), "r"(a[2]), "r"(a[3]), "r"(b0), "r"(b1));
}

// ---------------- prep: u/w vectors + gso bitmap ----------------
__global__ void gat_prep(const float* __restrict__ Wq, const float* __restrict__ Wk,
                         const float* __restrict__ a_src, const float* __restrict__ a_dst,
                         const int* __restrict__ gso) {
  const int tid = threadIdx.x;
  if (blockIdx.x == 0 && tid < 256) {
    int part = tid >> 6;           // 0,1: u(h0,h1)  2,3: w(h0,h1)
    int h = part & 1;
    int c = tid & 63;
    const float* W = (part < 2) ? Wq : Wk;
    const float* a = (part < 2) ? a_src : a_dst;
    float s = 0.f;
#pragma unroll
    for (int d = 0; d < 32; ++d) s += W[(h * 32 + d) * 64 + c] * a[h * 32 + d];
    g_uw[tid] = s;
  }
  const int warp = tid >> 5, lane = tid & 31;
  for (int wId = blockIdx.x * 8 + warp; wId < 5200; wId += gridDim.x * 8) {
    int r = wId / 13, wj = wId - r * 13;
    int j = wj * 32 + lane;
    int v = (j < 400) ? gso[r * 400 + j] : 0;
    unsigned m = __ballot_sync(0xffffffffu, v != 0);
    if (lane == 0) g_bm[r * 16 + wj] = m;
  }
}

// ---------------- fused main kernel ----------------
// smem bytes: VHL 102400 | E 12800 | Bit 27200 | Wv 16384 | UW 1024 | LN 512
#define OFF_HL   0
#define OFF_E    102400
#define OFF_BIT  115200
#define OFF_WVF  142400
#define OFF_UWF  158784
#define OFF_LNF  159808
#define SMF_BYTES 160320

typedef unsigned long long ull;

__global__ void __launch_bounds__(800, 1)
gat_fused(const float* __restrict__ x, const float* __restrict__ Wv,
          const float* __restrict__ ln_g, const float* __restrict__ ln_b,
          float* __restrict__ out) {
  extern __shared__ char sm[];
  // V interleaved layout: row d (800 halfwords = 1600B):
  //   group jg = j>>2 (16B): halfwords [0..3] = Vhi[j4..j4+3], [4..7] = Vlo[...]
  __nv_bfloat16* sHL = (__nv_bfloat16*)(sm + OFF_HL);
  float* sE = (float*)(sm + OFF_E);                     // [8][400]
  unsigned* sBit = (unsigned*)(sm + OFF_BIT);           // [400][17]
  float* sWv = (float*)(sm + OFF_WVF);
  float* sUW = (float*)(sm + OFF_UWF);
  float* sLN = (float*)(sm + OFF_LNF);

  const int tid = threadIdx.x, bt = blockIdx.x;
  const int b = bt >> 5, t_ = bt & 31;

  // prologue
  for (int i = tid; i < 4096; i += 800) sWv[i] = Wv[i];
  for (int i = tid; i < 256; i += 800) sUW[i] = g_uw[i];
  for (int i = tid; i < 6400; i += 800) sBit[(i >> 4) * 17 + (i & 15)] = g_bm[i];
  for (int i = tid; i < 64; i += 800) { sLN[i] = ln_g[i]; sLN[64 + i] = ln_b[i]; }
  __syncthreads();

  // ---- Phase A: scores + V projection (row split across 2 threads by d-half) ----
  {
    const int half = (tid >= 400) ? 1 : 0;
    const int row = tid - half * 400;
    const float* xb = x + (size_t)b * 819200 + (size_t)t_ * 400 + row;
    float xr[64];
#pragma unroll
    for (int c = 0; c < 64; ++c) xr[c] = xb[(size_t)c * 12800];

    if (!half) {
      float s0 = 0.f, s1 = 0.f, d0 = 0.f, d1 = 0.f;
#pragma unroll
      for (int c = 0; c < 64; ++c) {
        float xc = xr[c];
        s0 += xc * sUW[c];       s1 += xc * sUW[64 + c];
        d0 += xc * sUW[128 + c]; d1 += xc * sUW[192 + c];
      }
      sE[row]        = __expf(s0);        sE[400 + row]  = __expf(s1);         // Ae
      sE[800 + row]  = __expf(0.2f * s0); sE[1200 + row] = __expf(0.2f * s1);  // Ce
      sE[1600 + row] = __expf(d0);        sE[2000 + row] = __expf(d1);         // Be
      sE[2400 + row] = __expf(0.2f * d0); sE[2800 + row] = __expf(0.2f * d1);  // De
    }

    const float4* wv4 = (const float4*)sWv;
    const int d0c = half * 32;
    const int jslot = (row >> 2) * 8 + (row & 3);       // interleaved position
#pragma unroll 2
    for (int dd = 0; dd < 32; ++dd) {
      const int d = d0c + dd;
      float a0 = 0.f, a1 = 0.f, a2 = 0.f, a3 = 0.f;
#pragma unroll
      for (int q = 0; q < 16; ++q) {
        float4 w = wv4[d * 16 + q];   // broadcast (per half)
        a0 += xr[4 * q + 0] * w.x; a1 += xr[4 * q + 1] * w.y;
        a2 += xr[4 * q + 2] * w.z; a3 += xr[4 * q + 3] * w.w;
      }
      float v = (a0 + a1) + (a2 + a3);
      __nv_bfloat16 h = __float2bfloat16(v);
      sHL[d * 800 + jslot]     = h;
      sHL[d * 800 + jslot + 4] = __float2bfloat16(v - __bfloat162float(h));
    }
  }
  __syncthreads();

  // ---- Phase B: MMA attention + LN + transposed store (25 warps, 1 task each) ----
  // k-permutation: MMA-k {2tq,2tq+1} -> j {jb+4tq, +1}; {2tq+8,2tq+9} -> j {jb+4tq+2, +3}
  const int warp = tid >> 5, lane = tid & 31;
  const int g = lane >> 2, tq = lane & 3;
  float* obase = out + (size_t)b * 819200 + (size_t)t_ * 400;

  {
    const int i0 = warp * 16;
    const int r0 = i0 + g, r1 = r0 + 8;

    float Aer[2][2], Cer[2][2];
#pragma unroll
    for (int h = 0; h < 2; ++h) {
      Aer[h][0] = sE[h * 400 + r0];        Aer[h][1] = sE[h * 400 + r1];
      Cer[h][0] = sE[(2 + h) * 400 + r0];  Cer[h][1] = sE[(2 + h) * 400 + r1];
    }
    float C[8][4];
#pragma unroll
    for (int nt = 0; nt < 8; ++nt)
#pragma unroll
      for (int q = 0; q < 4; ++q) C[nt][q] = 0.f;
    float Cz[2][4];
#pragma unroll
    for (int h = 0; h < 2; ++h)
#pragma unroll
      for (int q = 0; q < 4; ++q) Cz[h][q] = 0.f;

    for (int js = 0; js < 25; ++js) {
      const int jb = js * 16;
      const unsigned wd0 = sBit[r0 * 17 + (jb >> 5)];
      const unsigned wd1 = sBit[r1 * 17 + (jb >> 5)];
      const int sh = (jb & 16) + 4 * tq;
      const unsigned n0 = (wd0 >> sh) & 0xFu;
      const unsigned n1 = (wd1 >> sh) & 0xFu;
      unsigned mk[4];
      mk[0] = ((n0 & 1u) ? 0x0000FFFFu : 0u) | ((n0 & 2u) ? 0xFFFF0000u : 0u);
      mk[1] = ((n1 & 1u) ? 0x0000FFFFu : 0u) | ((n1 & 2u) ? 0xFFFF0000u : 0u);
      mk[2] = ((n0 & 4u) ? 0x0000FFFFu : 0u) | ((n0 & 8u) ? 0xFFFF0000u : 0u);
      mk[3] = ((n1 & 4u) ? 0x0000FFFFu : 0u) | ((n1 & 8u) ? 0xFFFF0000u : 0u);
      const int j4 = jb + 4 * tq;

#pragma unroll
      for (int h = 0; h < 2; ++h) {
        const float4 Be = *(const float4*)(sE + (4 + h) * 400 + j4);
        const float4 De = *(const float4*)(sE + (6 + h) * 400 + j4);
        const float A0 = Aer[h][0], A1 = Aer[h][1];
        const float Q0 = Cer[h][0], Q1 = Cer[h][1];

        // exp(lrelu(si+sj)) = max(Ae*Be, Ce*De)
        const float p00 = fmaxf(A0 * Be.x, Q0 * De.x);
        const float p01 = fmaxf(A0 * Be.y, Q0 * De.y);
        const float p02 = fmaxf(A0 * Be.z, Q0 * De.z);
        const float p03 = fmaxf(A0 * Be.w, Q0 * De.w);
        const float p10 = fmaxf(A1 * Be.x, Q1 * De.x);
        const float p11 = fmaxf(A1 * Be.y, Q1 * De.y);
        const float p12 = fmaxf(A1 * Be.z, Q1 * De.z);
        const float p13 = fmaxf(A1 * Be.w, Q1 * De.w);

        const unsigned h0 = bf2pack(p01, p00);
        const unsigned h1 = bf2pack(p11, p10);
        const unsigned h2 = bf2pack(p03, p02);
        const unsigned h3 = bf2pack(p13, p12);
        unsigned ah[4], al[4];
        al[0] = bf2pack(p01 - up_hi(h0), p00 - up_lo(h0)) & mk[0];
        al[1] = bf2pack(p11 - up_hi(h1), p10 - up_lo(h1)) & mk[1];
        al[2] = bf2pack(p03 - up_hi(h2), p02 - up_lo(h2)) & mk[2];
        al[3] = bf2pack(p13 - up_hi(h3), p12 - up_lo(h3)) & mk[3];
        ah[0] = h0 & mk[0]; ah[1] = h1 & mk[1];
        ah[2] = h2 & mk[2]; ah[3] = h3 & mk[3];

        // Z via constant-ones B fragment
        mma16816(Cz[h], ah, 0x3F803F80u, 0x3F803F80u);
        mma16816(Cz[h], al, 0x3F803F80u, 0x3F803F80u);

#pragma unroll
        for (int nt = 0; nt < 4; ++nt) {
          const int d = h * 32 + nt * 8 + g;
          // one LDS.128: (bh0,bh1,bl0,bl1) — conflict-free by construction
          const uint4 bv = *(const uint4*)(sHL + d * 800 + 2 * j4);
          float* Cp = C[h * 4 + nt];
          mma16816(Cp, ah, bv.x, bv.y);   // hi*hi
          mma16816(Cp, al, bv.x, bv.y);   // lo*hi
          mma16816(Cp, ah, bv.z, bv.w);   // hi*lo
        }
      }
    }

    // normalize by Z (in-register: Cz[h][0]=z(r0), Cz[h][2]=z(r1))
    float rzv[2][2];
#pragma unroll
    for (int h = 0; h < 2; ++h) {
      rzv[h][0] = 1.f / Cz[h][0];
      rzv[h][1] = 1.f / Cz[h][2];
    }
#pragma unroll
    for (int nt = 0; nt < 8; ++nt) {
      const int h = nt >> 2;
      C[nt][0] *= rzv[h][0]; C[nt][1] *= rzv[h][0];
      C[nt][2] *= rzv[h][1]; C[nt][3] *= rzv[h][1];
    }

    // LayerNorm per row + transposed store
#pragma unroll
    for (int rh = 0; rh < 2; ++rh) {
      float s = 0.f, ss = 0.f;
#pragma unroll
      for (int nt = 0; nt < 8; ++nt) {
        float o0 = C[nt][rh * 2], o1 = C[nt][rh * 2 + 1];
        s += o0 + o1; ss += o0 * o0 + o1 * o1;
      }
      s  += __shfl_xor_sync(0xffffffffu, s, 1);  s  += __shfl_xor_sync(0xffffffffu, s, 2);
      ss += __shfl_xor_sync(0xffffffffu, ss, 1); ss += __shfl_xor_sync(0xffffffffu, ss, 2);
      const float mu = s * (1.f / 64.f);
      const float var = ss * (1.f / 64.f) - mu * mu;
      const float rs = rsqrtf(var + 1e-5f);
      const int n = i0 + g + rh * 8;
#pragma unroll
      for (int nt = 0; nt < 8; ++nt) {
        const int d0 = nt * 8 + 2 * tq;
        float o0 = (C[nt][rh * 2] - mu) * rs * sLN[d0] + sLN[64 + d0];
        float o1 = (C[nt][rh * 2 + 1] - mu) * rs * sLN[d0 + 1] + sLN[64 + d0 + 1];
        obase[(size_t)d0 * 12800 + n] = o0;
        obase[(size_t)(d0 + 1) * 12800 + n] = o1;
      }
    }
  }
}

extern "C" void kernel_launch(void* const* d_in, const int* in_sizes, int n_in,
                              void* d_out, int out_size) {
  const float* x     = (const float*)d_in[0];
  const float* Wq    = (const float*)d_in[1];
  const float* Wk    = (const float*)d_in[2];
  const float* Wv    = (const float*)d_in[3];
  const float* a_src = (const float*)d_in[4];
  const float* a_dst = (const float*)d_in[5];
  const float* ln_g  = (const float*)d_in[6];
  const float* ln_b  = (const float*)d_in[7];
  const int*   gso   = (const int*)d_in[8];
  float* out = (float*)d_out;

  cudaFuncSetAttribute(gat_fused, cudaFuncAttributeMaxDynamicSharedMemorySize, SMF_BYTES);
  gat_prep<<<52, 256>>>(Wq, Wk, a_src, a_dst, gso);
  gat_fused<<<256, 800, SMF_BYTES>>>(x, Wv, ln_g, ln_b, out);
}

// round 10
// speedup vs baseline: 1.3145x; 1.3145x over previous
#include <cuda_runtime.h>
#include <cuda_bf16.h>

// ---------------- device scratch (static) ----------------
__device__ float g_uw[256];          // u/w projection vectors
__device__ unsigned g_bm[400 * 16];  // gso bitmap [i][word]

typedef unsigned long long ull;

// ---------------- helpers ----------------
__device__ __forceinline__ unsigned bf2pack(float hi, float lo) {
  unsigned r;
  asm("cvt.rn.bf16x2.f32 %0, %1, %2;" : "=r"(r) : "f"(hi), "f"(lo));
  return r;
}
__device__ __forceinline__ float up_hi(unsigned r) { return __uint_as_float(r & 0xFFFF0000u); }
__device__ __forceinline__ float up_lo(unsigned r) { return __uint_as_float(r << 16); }
__device__ __forceinline__ unsigned s2u(const void* p) {
  return (unsigned)__cvta_generic_to_shared(p);
}

__device__ __forceinline__ void mma16816(float* c, const unsigned* a, unsigned b0, unsigned b1) {
  asm volatile(
      "mma.sync.aligned.m16n8k16.row.col.f32.bf16.bf16.f32 "
      "{%0,%1,%2,%3}, {%4,%5,%6,%7}, {%8,%9}, {%0,%1,%2,%3};"
      : "+f"(c[0]), "+f"(c[1]), "+f"(c[2]), "+f"(c[3])
      : "r"(a[0]), "r"(a[1]), "r"(a[2]), "r"(a[3]), "r"(b0), "r"(b1));
}

#define LDMX4(r0, r1, r2, r3, addr)                                        \
  asm volatile("ldmatrix.sync.aligned.m8n8.x4.shared.b16 {%0,%1,%2,%3}, [%4];" \
               : "=r"(r0), "=r"(r1), "=r"(r2), "=r"(r3) : "r"(addr))

#define STMX4T(addr, r0, r1, r2, r3)                                       \
  asm volatile("stmatrix.sync.aligned.m8n8.x4.trans.shared.b16 [%0], {%1,%2,%3,%4};" \
               :: "r"(addr), "r"(r0), "r"(r1), "r"(r2), "r"(r3))

// ---------------- prep: u/w vectors + gso bitmap ----------------
__global__ void gat_prep(const float* __restrict__ Wq, const float* __restrict__ Wk,
                         const float* __restrict__ a_src, const float* __restrict__ a_dst,
                         const int* __restrict__ gso) {
  const int tid = threadIdx.x;
  if (blockIdx.x == 0 && tid < 256) {
    int part = tid >> 6;           // 0,1: u(h0,h1)  2,3: w(h0,h1)
    int h = part & 1;
    int c = tid & 63;
    const float* W = (part < 2) ? Wq : Wk;
    const float* a = (part < 2) ? a_src : a_dst;
    float s = 0.f;
#pragma unroll
    for (int d = 0; d < 32; ++d) s += W[(h * 32 + d) * 64 + c] * a[h * 32 + d];
    g_uw[tid] = s;
  }
  const int warp = tid >> 5, lane = tid & 31;
  for (int wId = blockIdx.x * 8 + warp; wId < 5200; wId += gridDim.x * 8) {
    int r = wId / 13, wj = wId - r * 13;
    int j = wj * 32 + lane;
    int v = (j < 400) ? gso[r * 400 + j] : 0;
    unsigned m = __ballot_sync(0xffffffffu, v != 0);
    if (lane == 0) g_bm[r * 16 + wj] = m;
  }
}

// ---------------- fused main kernel ----------------
// smem: [0,115200) = x staging (xHi [400][72]@0, xLo@57600), later V planes
//       (vHi [64][400]@0, vLo@51200). Then E | Bit | WvH | WvL | LN | UW.
#define OFF_X    0
#define OFF_XLO  57600
#define OFF_VLO  51200
#define OFF_E    115200
#define OFF_BIT  128000
#define OFF_WVH  155200
#define OFF_WVL  164416
#define OFF_LN   173632
#define OFF_UW   174144
#define SMF_BYTES 175168

__global__ void __launch_bounds__(800, 1)
gat_fused(const float* __restrict__ x, const float* __restrict__ Wv,
          const float* __restrict__ ln_g, const float* __restrict__ ln_b,
          float* __restrict__ out) {
  extern __shared__ char sm[];
  float* sE = (float*)(sm + OFF_E);                     // [8][400]
  unsigned* sBit = (unsigned*)(sm + OFF_BIT);           // [400][17]
  __nv_bfloat16* sWvH = (__nv_bfloat16*)(sm + OFF_WVH); // [64][72]
  __nv_bfloat16* sWvL = (__nv_bfloat16*)(sm + OFF_WVL);
  float* sLN = (float*)(sm + OFF_LN);
  float* sUW = (float*)(sm + OFF_UW);

  const int tid = threadIdx.x, bt = blockIdx.x;
  const int b = bt >> 5, t_ = bt & 31;

  // ---- prologue ----
  for (int i = tid; i < 4096; i += 800) {
    float v = Wv[i];
    int d = i >> 6, c = i & 63;
    __nv_bfloat16 h = __float2bfloat16(v);
    sWvH[d * 72 + c] = h;
    sWvL[d * 72 + c] = __float2bfloat16(v - __bfloat162float(h));
  }
  for (int i = tid; i < 256; i += 800) sUW[i] = g_uw[i];
  for (int i = tid; i < 6400; i += 800) sBit[(i >> 4) * 17 + (i & 15)] = g_bm[i];
  for (int i = tid; i < 64; i += 800) { sLN[i] = ln_g[i]; sLN[64 + i] = ln_b[i]; }
  __syncthreads();

  // ---- staging: scores + exps + x hi/lo split into planes ----
  if (tid < 400) {
    const int r = tid;
    const float* xb = x + (size_t)b * 819200 + (size_t)t_ * 400 + r;
    float xr[64];
#pragma unroll
    for (int c = 0; c < 64; ++c) xr[c] = xb[(size_t)c * 12800];

    float s0 = 0.f, s1 = 0.f, d0 = 0.f, d1 = 0.f;
#pragma unroll
    for (int c = 0; c < 64; ++c) {
      float xc = xr[c];
      s0 += xc * sUW[c];       s1 += xc * sUW[64 + c];
      d0 += xc * sUW[128 + c]; d1 += xc * sUW[192 + c];
    }
    sE[r]        = __expf(s0);        sE[400 + r]  = __expf(s1);         // Ae
    sE[800 + r]  = __expf(0.2f * s0); sE[1200 + r] = __expf(0.2f * s1);  // Ce
    sE[1600 + r] = __expf(d0);        sE[2000 + r] = __expf(d1);         // Be
    sE[2400 + r] = __expf(0.2f * d0); sE[2800 + r] = __expf(0.2f * d1);  // De

#pragma unroll
    for (int cb = 0; cb < 64; cb += 8) {
      unsigned hp[4], lp[4];
#pragma unroll
      for (int q2 = 0; q2 < 4; ++q2) {
        float e = xr[cb + 2 * q2], o = xr[cb + 2 * q2 + 1];
        unsigned hh = bf2pack(o, e);
        hp[q2] = hh;
        lp[q2] = bf2pack(o - up_hi(hh), e - up_lo(hh));
      }
      *(uint4*)(sm + OFF_X + r * 144 + cb * 2) = make_uint4(hp[0], hp[1], hp[2], hp[3]);
      *(uint4*)(sm + OFF_XLO + r * 144 + cb * 2) = make_uint4(lp[0], lp[1], lp[2], lp[3]);
    }
  }
  __syncthreads();

  const int warp = tid >> 5, lane = tid & 31;
  const int g = lane >> 2, tq = lane & 3;
  const int mm = lane >> 3, rr = lane & 7;
  const int i0 = warp * 16;

  // ---- Phase A GEMM: V = x @ Wv^T via hi/lo bf16 MMA ----
  float C[8][4];
#pragma unroll
  for (int nt = 0; nt < 8; ++nt)
#pragma unroll
    for (int q = 0; q < 4; ++q) C[nt][q] = 0.f;
  {
    const unsigned xH = s2u(sm) + (unsigned)((i0 + 8 * (mm & 1) + rr) * 144 + (mm >> 1) * 16);
    const unsigned xL = xH + OFF_XLO;
    const unsigned wH = s2u(sm + OFF_WVH) + (unsigned)(rr * 144 + (mm & 1) * 16 + (mm >> 1) * 1152);
    const unsigned wL = wH + (OFF_WVL - OFF_WVH);

#pragma unroll
    for (int kk = 0; kk < 4; ++kk) {
      unsigned ah[4], al[4];
      LDMX4(ah[0], ah[1], ah[2], ah[3], xH + kk * 32);
      LDMX4(al[0], al[1], al[2], al[3], xL + kk * 32);
#pragma unroll
      for (int ntp = 0; ntp < 4; ++ntp) {
        unsigned bh[4], bl[4];
        LDMX4(bh[0], bh[1], bh[2], bh[3], wH + ntp * 2304 + kk * 32);
        LDMX4(bl[0], bl[1], bl[2], bl[3], wL + ntp * 2304 + kk * 32);
        mma16816(C[2 * ntp], ah, bh[0], bh[1]);
        mma16816(C[2 * ntp], al, bh[0], bh[1]);
        mma16816(C[2 * ntp], ah, bl[0], bl[1]);
        mma16816(C[2 * ntp + 1], ah, bh[2], bh[3]);
        mma16816(C[2 * ntp + 1], al, bh[2], bh[3]);
        mma16816(C[2 * ntp + 1], ah, bl[2], bl[3]);
      }
    }
  }
  __syncthreads();   // all GEMM reads of x staging complete

  // ---- epilogue: C -> hi/lo bf16 -> V planes via stmatrix.trans ----
  {
    const int t8 = lane & 7;
    const int ntoff = (mm >> 1), rhm = mm & 1;
#pragma unroll
    for (int q = 0; q < 4; ++q) {
      unsigned hi[4], lo[4];
      hi[0] = bf2pack(C[2 * q][1],     C[2 * q][0]);
      hi[1] = bf2pack(C[2 * q][3],     C[2 * q][2]);
      hi[2] = bf2pack(C[2 * q + 1][1], C[2 * q + 1][0]);
      hi[3] = bf2pack(C[2 * q + 1][3], C[2 * q + 1][2]);
      lo[0] = bf2pack(C[2 * q][1] - up_hi(hi[0]),     C[2 * q][0] - up_lo(hi[0]));
      lo[1] = bf2pack(C[2 * q][3] - up_hi(hi[1]),     C[2 * q][2] - up_lo(hi[1]));
      lo[2] = bf2pack(C[2 * q + 1][1] - up_hi(hi[2]), C[2 * q + 1][0] - up_lo(hi[2]));
      lo[3] = bf2pack(C[2 * q + 1][3] - up_hi(hi[3]), C[2 * q + 1][2] - up_lo(hi[3]));
      const int ntm = 2 * q + ntoff;
      const unsigned sa = s2u(sm) + (unsigned)((8 * ntm + t8) * 800 + (i0 + 8 * rhm) * 2);
      STMX4T(sa, hi[0], hi[1], hi[2], hi[3]);
      STMX4T(sa + OFF_VLO, lo[0], lo[1], lo[2], lo[3]);
    }
  }
  __syncthreads();

  // ---- Phase B: MMA attention + LN + transposed store ----
  float* obase = out + (size_t)b * 819200 + (size_t)t_ * 400;
  {
    const int r0 = i0 + g, r1 = r0 + 8;

    float Aer[2][2], Cer[2][2];
#pragma unroll
    for (int h = 0; h < 2; ++h) {
      Aer[h][0] = sE[h * 400 + r0];        Aer[h][1] = sE[h * 400 + r1];
      Cer[h][0] = sE[(2 + h) * 400 + r0];  Cer[h][1] = sE[(2 + h) * 400 + r1];
    }
#pragma unroll
    for (int nt = 0; nt < 8; ++nt)
#pragma unroll
      for (int q = 0; q < 4; ++q) C[nt][q] = 0.f;
    float Cz[2][4];
#pragma unroll
    for (int h = 0; h < 2; ++h)
#pragma unroll
      for (int q = 0; q < 4; ++q) Cz[h][q] = 0.f;

    for (int js = 0; js < 25; ++js) {
      const int jb = js * 16;
      const unsigned wd0 = sBit[r0 * 17 + (jb >> 5)];
      const unsigned wd1 = sBit[r1 * 17 + (jb >> 5)];
      const int sh = (jb & 16) + 4 * tq;
      const unsigned n0 = (wd0 >> sh) & 0xFu;
      const unsigned n1 = (wd1 >> sh) & 0xFu;
      unsigned mk[4];
      mk[0] = ((n0 & 1u) ? 0x0000FFFFu : 0u) | ((n0 & 2u) ? 0xFFFF0000u : 0u);
      mk[1] = ((n1 & 1u) ? 0x0000FFFFu : 0u) | ((n1 & 2u) ? 0xFFFF0000u : 0u);
      mk[2] = ((n0 & 4u) ? 0x0000FFFFu : 0u) | ((n0 & 8u) ? 0xFFFF0000u : 0u);
      mk[3] = ((n1 & 4u) ? 0x0000FFFFu : 0u) | ((n1 & 8u) ? 0xFFFF0000u : 0u);
      const int j4 = jb + 4 * tq;

#pragma unroll
      for (int h = 0; h < 2; ++h) {
        const float4 Be = *(const float4*)(sE + (4 + h) * 400 + j4);
        const float4 De = *(const float4*)(sE + (6 + h) * 400 + j4);
        const float A0 = Aer[h][0], A1 = Aer[h][1];
        const float Q0 = Cer[h][0], Q1 = Cer[h][1];

        // exp(lrelu(si+sj)) = max(Ae*Be, Ce*De)
        const float p00 = fmaxf(A0 * Be.x, Q0 * De.x);
        const float p01 = fmaxf(A0 * Be.y, Q0 * De.y);
        const float p02 = fmaxf(A0 * Be.z, Q0 * De.z);
        const float p03 = fmaxf(A0 * Be.w, Q0 * De.w);
        const float p10 = fmaxf(A1 * Be.x, Q1 * De.x);
        const float p11 = fmaxf(A1 * Be.y, Q1 * De.y);
        const float p12 = fmaxf(A1 * Be.z, Q1 * De.z);
        const float p13 = fmaxf(A1 * Be.w, Q1 * De.w);

        const unsigned h0 = bf2pack(p01, p00);
        const unsigned h1 = bf2pack(p11, p10);
        const unsigned h2 = bf2pack(p03, p02);
        const unsigned h3 = bf2pack(p13, p12);
        unsigned ah[4], al[4];
        al[0] = bf2pack(p01 - up_hi(h0), p00 - up_lo(h0)) & mk[0];
        al[1] = bf2pack(p11 - up_hi(h1), p10 - up_lo(h1)) & mk[1];
        al[2] = bf2pack(p03 - up_hi(h2), p02 - up_lo(h2)) & mk[2];
        al[3] = bf2pack(p13 - up_hi(h3), p12 - up_lo(h3)) & mk[3];
        ah[0] = h0 & mk[0]; ah[1] = h1 & mk[1];
        ah[2] = h2 & mk[2]; ah[3] = h3 & mk[3];

        // Z via constant-ones B fragment
        mma16816(Cz[h], ah, 0x3F803F80u, 0x3F803F80u);
        mma16816(Cz[h], al, 0x3F803F80u, 0x3F803F80u);

#pragma unroll
        for (int nt = 0; nt < 4; ++nt) {
          const int d = h * 32 + nt * 8 + g;
          const ull bh = *(const ull*)(sm + d * 800 + 2 * j4);            // vHi plane
          const ull bl = *(const ull*)(sm + OFF_VLO + d * 800 + 2 * j4);  // vLo plane
          float* Cp = C[h * 4 + nt];
          mma16816(Cp, ah, (unsigned)bh, (unsigned)(bh >> 32));  // hi*hi
          mma16816(Cp, al, (unsigned)bh, (unsigned)(bh >> 32));  // lo*hi
          mma16816(Cp, ah, (unsigned)bl, (unsigned)(bl >> 32));  // hi*lo
        }
      }
    }

    // normalize by Z
    float rzv[2][2];
#pragma unroll
    for (int h = 0; h < 2; ++h) {
      rzv[h][0] = 1.f / Cz[h][0];
      rzv[h][1] = 1.f / Cz[h][2];
    }
#pragma unroll
    for (int nt = 0; nt < 8; ++nt) {
      const int h = nt >> 2;
      C[nt][0] *= rzv[h][0]; C[nt][1] *= rzv[h][0];
      C[nt][2] *= rzv[h][1]; C[nt][3] *= rzv[h][1];
    }

    // LayerNorm per row + transposed store
#pragma unroll
    for (int rh = 0; rh < 2; ++rh) {
      float s = 0.f, ss = 0.f;
#pragma unroll
      for (int nt = 0; nt < 8; ++nt) {
        float o0 = C[nt][rh * 2], o1 = C[nt][rh * 2 + 1];
        s += o0 + o1; ss += o0 * o0 + o1 * o1;
      }
      s  += __shfl_xor_sync(0xffffffffu, s, 1);  s  += __shfl_xor_sync(0xffffffffu, s, 2);
      ss += __shfl_xor_sync(0xffffffffu, ss, 1); ss += __shfl_xor_sync(0xffffffffu, ss, 2);
      const float mu = s * (1.f / 64.f);
      const float var = ss * (1.f / 64.f) - mu * mu;
      const float rs = rsqrtf(var + 1e-5f);
      const int n = i0 + g + rh * 8;
#pragma unroll
      for (int nt = 0; nt < 8; ++nt) {
        const int d0 = nt * 8 + 2 * tq;
        float o0 = (C[nt][rh * 2] - mu) * rs * sLN[d0] + sLN[64 + d0];
        float o1 = (C[nt][rh * 2 + 1] - mu) * rs * sLN[d0 + 1] + sLN[64 + d0 + 1];
        obase[(size_t)d0 * 12800 + n] = o0;
        obase[(size_t)(d0 + 1) * 12800 + n] = o1;
      }
    }
  }
}

extern "C" void kernel_launch(void* const* d_in, const int* in_sizes, int n_in,
                              void* d_out, int out_size) {
  const float* x     = (const float*)d_in[0];
  const float* Wq    = (const float*)d_in[1];
  const float* Wk    = (const float*)d_in[2];
  const float* Wv    = (const float*)d_in[3];
  const float* a_src = (const float*)d_in[4];
  const float* a_dst = (const float*)d_in[5];
  const float* ln_g  = (const float*)d_in[6];
  const float* ln_b  = (const float*)d_in[7];
  const int*   gso   = (const int*)d_in[8];
  float* out = (float*)d_out;

  cudaFuncSetAttribute(gat_fused, cudaFuncAttributeMaxDynamicSharedMemorySize, SMF_BYTES);
  gat_prep<<<52, 256>>>(Wq, Wk, a_src, a_dst, gso);
  gat_fused<<<256, 800, SMF_BYTES>>>(x, Wv, ln_g, ln_b, out);
}

// round 11
// speedup vs baseline: 1.3654x; 1.0388x over previous
#include <cuda_runtime.h>
#include <cuda_fp16.h>

typedef unsigned long long ull;

// ---------------- device scratch (static) ----------------
__device__ float g_uw[256];                       // u/w projection vectors
__device__ unsigned g_bm[400 * 16];               // gso bitmap [i][word]
__device__ __align__(16) __half g_V[256 * 25600]; // V^T fp16 [graph][64][400]
__device__ __align__(16) float g_E[256 * 3200];   // Ae,Ce,Be,De [graph][8][400]

// ---------------- helpers ----------------
__device__ __forceinline__ unsigned f16pack(float hi, float lo) {
  unsigned r;
  asm("cvt.rn.f16x2.f32 %0, %1, %2;" : "=r"(r) : "f"(hi), "f"(lo));
  return r;
}
__device__ __forceinline__ float2 h2f(unsigned u) {
  __half2 h = *reinterpret_cast<__half2*>(&u);
  return __half22float2(h);   // .x = low half, .y = high half
}
__device__ __forceinline__ unsigned s2u(const void* p) {
  return (unsigned)__cvta_generic_to_shared(p);
}
__device__ __forceinline__ void mma16816(float* c, const unsigned* a, unsigned b0, unsigned b1) {
  asm volatile(
      "mma.sync.aligned.m16n8k16.row.col.f32.f16.f16.f32 "
      "{%0,%1,%2,%3}, {%4,%5,%6,%7}, {%8,%9}, {%0,%1,%2,%3};"
      : "+f"(c[0]), "+f"(c[1]), "+f"(c[2]), "+f"(c[3])
      : "r"(a[0]), "r"(a[1]), "r"(a[2]), "r"(a[3]), "r"(b0), "r"(b1));
}
#define LDMX4(r0, r1, r2, r3, addr)                                        \
  asm volatile("ldmatrix.sync.aligned.m8n8.x4.shared.b16 {%0,%1,%2,%3}, [%4];" \
               : "=r"(r0), "=r"(r1), "=r"(r2), "=r"(r3) : "r"(addr))
#define STMX4T(addr, r0, r1, r2, r3)                                       \
  asm volatile("stmatrix.sync.aligned.m8n8.x4.trans.shared.b16 [%0], {%1,%2,%3,%4};" \
               :: "r"(addr), "r"(r0), "r"(r1), "r"(r2), "r"(r3))

// ---------------- prep: u/w vectors + gso bitmap ----------------
__global__ void gat_prep(const float* __restrict__ Wq, const float* __restrict__ Wk,
                         const float* __restrict__ a_src, const float* __restrict__ a_dst,
                         const int* __restrict__ gso) {
  const int tid = threadIdx.x;
  if (blockIdx.x == 0 && tid < 256) {
    int part = tid >> 6;
    int h = part & 1;
    int c = tid & 63;
    const float* W = (part < 2) ? Wq : Wk;
    const float* a = (part < 2) ? a_src : a_dst;
    float s = 0.f;
#pragma unroll
    for (int d = 0; d < 32; ++d) s += W[(h * 32 + d) * 64 + c] * a[h * 32 + d];
    g_uw[tid] = s;
  }
  const int warp = tid >> 5, lane = tid & 31;
  for (int wId = blockIdx.x * 8 + warp; wId < 5200; wId += gridDim.x * 8) {
    int r = wId / 13, wj = wId - r * 13;
    int j = wj * 32 + lane;
    int v = (j < 400) ? gso[r * 400 + j] : 0;
    unsigned m = __ballot_sync(0xffffffffu, v != 0);
    if (lane == 0) g_bm[r * 16 + wj] = m;
  }
}

// ---------------- K1: stage (scores + V projection via fp16 MMA) ----------------
// smem: x fp16 [400][72] @0 (57600) | WvH [64][72] @57600 (9216) | WvL @66816 | UW @76032
// after GEMM, V fp16 [64][400] overlays @0 (51200)
#define K1_WVH 57600
#define K1_WVL 66816
#define K1_UW  76032
#define K1_BYTES 77056

__global__ void __launch_bounds__(800, 1)
gat_stage(const float* __restrict__ x, const float* __restrict__ Wv) {
  extern __shared__ char sm[];
  __half* sWvH = (__half*)(sm + K1_WVH);
  __half* sWvL = (__half*)(sm + K1_WVL);
  float* sUW = (float*)(sm + K1_UW);

  const int tid = threadIdx.x, bt = blockIdx.x;
  const int b = bt >> 5, t_ = bt & 31;

  for (int i = tid; i < 4096; i += 800) {
    float w = Wv[i];
    __half wh = __float2half(w);
    int d = i >> 6, c = i & 63;
    sWvH[d * 72 + c] = wh;
    sWvL[d * 72 + c] = __float2half(w - __half2float(wh));
  }
  for (int i = tid; i < 256; i += 800) sUW[i] = g_uw[i];
  __syncthreads();

  // staging: thread r owns row r (scores -> g_E, x -> fp16 smem)
  if (tid < 400) {
    const int r = tid;
    const float* xb = x + (size_t)b * 819200 + (size_t)t_ * 400 + r;
    float xr[64];
#pragma unroll
    for (int c = 0; c < 64; ++c) xr[c] = xb[(size_t)c * 12800];

    float s0 = 0.f, s1 = 0.f, d0 = 0.f, d1 = 0.f;
#pragma unroll
    for (int c = 0; c < 64; ++c) {
      float xc = xr[c];
      s0 += xc * sUW[c];       s1 += xc * sUW[64 + c];
      d0 += xc * sUW[128 + c]; d1 += xc * sUW[192 + c];
    }
    float* E = g_E + (size_t)bt * 3200;
    E[r]        = __expf(s0);        E[400 + r]  = __expf(s1);
    E[800 + r]  = __expf(0.2f * s0); E[1200 + r] = __expf(0.2f * s1);
    E[1600 + r] = __expf(d0);        E[2000 + r] = __expf(d1);
    E[2400 + r] = __expf(0.2f * d0); E[2800 + r] = __expf(0.2f * d1);

#pragma unroll
    for (int cb = 0; cb < 64; cb += 8) {
      unsigned hp[4];
#pragma unroll
      for (int q2 = 0; q2 < 4; ++q2)
        hp[q2] = f16pack(xr[cb + 2 * q2 + 1], xr[cb + 2 * q2]);
      *(uint4*)(sm + r * 144 + cb * 2) = make_uint4(hp[0], hp[1], hp[2], hp[3]);
    }
  }
  __syncthreads();

  const int warp = tid >> 5, lane = tid & 31;
  const int mm = lane >> 3, rr = lane & 7;
  const int i0 = warp * 16;

  // GEMM: V = x(fp16) @ (WvH + WvL)^T ; 25 warps, one 16-row tile each
  float C[8][4];
#pragma unroll
  for (int nt = 0; nt < 8; ++nt)
#pragma unroll
    for (int q = 0; q < 4; ++q) C[nt][q] = 0.f;
  {
    const unsigned xA = s2u(sm) + (unsigned)((i0 + 8 * (mm & 1) + rr) * 144 + (mm >> 1) * 16);
    const unsigned wH = s2u(sm + K1_WVH) + (unsigned)(rr * 144 + (mm & 1) * 16 + (mm >> 1) * 1152);
    const unsigned wL = wH + (unsigned)(K1_WVL - K1_WVH);
#pragma unroll
    for (int kk = 0; kk < 4; ++kk) {
      unsigned a[4];
      LDMX4(a[0], a[1], a[2], a[3], xA + kk * 32);
#pragma unroll
      for (int ntp = 0; ntp < 4; ++ntp) {
        unsigned bh[4], bl[4];
        LDMX4(bh[0], bh[1], bh[2], bh[3], wH + ntp * 2304 + kk * 32);
        LDMX4(bl[0], bl[1], bl[2], bl[3], wL + ntp * 2304 + kk * 32);
        mma16816(C[2 * ntp], a, bh[0], bh[1]);
        mma16816(C[2 * ntp], a, bl[0], bl[1]);
        mma16816(C[2 * ntp + 1], a, bh[2], bh[3]);
        mma16816(C[2 * ntp + 1], a, bl[2], bl[3]);
      }
    }
  }
  __syncthreads();   // all x reads done

  // epilogue: C -> fp16 -> V plane via stmatrix.trans (overlay @0)
  {
    const int t8 = lane & 7;
    const int ntoff = (mm >> 1), rhm = mm & 1;
#pragma unroll
    for (int q = 0; q < 4; ++q) {
      unsigned hv[4];
      hv[0] = f16pack(C[2 * q][1],     C[2 * q][0]);
      hv[1] = f16pack(C[2 * q][3],     C[2 * q][2]);
      hv[2] = f16pack(C[2 * q + 1][1], C[2 * q + 1][0]);
      hv[3] = f16pack(C[2 * q + 1][3], C[2 * q + 1][2]);
      const int ntm = 2 * q + ntoff;
      const unsigned sa = s2u(sm) + (unsigned)((8 * ntm + t8) * 800 + (i0 + 8 * rhm) * 2);
      STMX4T(sa, hv[0], hv[1], hv[2], hv[3]);
    }
  }
  __syncthreads();

  // writeout V to gmem
  uint4* dv = (uint4*)(g_V + (size_t)bt * 25600);
  const uint4* sv = (const uint4*)sm;
  for (int i = tid; i < 3200; i += 800) dv[i] = sv[i];
}

// ---------------- K2: attention + LN (2 CTAs/SM) ----------------
// smem: V fp16 [64][400] @0 (51200) | E @51200 (12800) | Bit @64000 (27200, stride 17)
//       | LN @91200 (512) | pairScr @91712 (2048)
#define K2_E    51200
#define K2_BIT  64000
#define K2_LN   91200
#define K2_SCR  91712
#define K2_BYTES 93760

__global__ void __launch_bounds__(512, 2)
gat_attn(const float* __restrict__ ln_g, const float* __restrict__ ln_b,
         float* __restrict__ out) {
  extern __shared__ char sm[];
  float* sE = (float*)(sm + K2_E);
  unsigned* sBit = (unsigned*)(sm + K2_BIT);
  float* sLN = (float*)(sm + K2_LN);
  float* sScr = (float*)(sm + K2_SCR);

  const int tid = threadIdx.x, bt = blockIdx.x;
  const int b = bt >> 5, t_ = bt & 31;

  {  // prologue
    uint4* v4 = (uint4*)sm;
    const uint4* gv = (const uint4*)(g_V + (size_t)bt * 25600);
    for (int i = tid; i < 3200; i += 512) v4[i] = gv[i];
    uint4* e4 = (uint4*)sE;
    const uint4* ge = (const uint4*)(g_E + (size_t)bt * 3200);
    for (int i = tid; i < 800; i += 512) e4[i] = ge[i];
    for (int i = tid; i < 6400; i += 512) sBit[(i >> 4) * 17 + (i & 15)] = g_bm[i];
    for (int i = tid; i < 64; i += 512) { sLN[i] = ln_g[i]; sLN[64 + i] = ln_b[i]; }
  }
  __syncthreads();

  const int warp = tid >> 5, lane = tid & 31;
  const int g = lane >> 2, tq = lane & 3;
  const int pair = warp >> 1, h = warp & 1;
  float* obase = out + (size_t)b * 819200 + (size_t)t_ * 400;

  for (int t = pair; t < 25; t += 8) {
    const int i0 = t * 16;
    const int r0 = i0 + g, r1 = r0 + 8;
    const float A0 = sE[h * 400 + r0],       A1 = sE[h * 400 + r1];
    const float Q0 = sE[(2 + h) * 400 + r0], Q1 = sE[(2 + h) * 400 + r1];

    float C[4][4];
#pragma unroll
    for (int nt = 0; nt < 4; ++nt)
#pragma unroll
      for (int q = 0; q < 4; ++q) C[nt][q] = 0.f;
    float Cz[4] = {0.f, 0.f, 0.f, 0.f};

    for (int js = 0; js < 25; ++js) {
      const int jb = js * 16;
      const unsigned wd0 = sBit[r0 * 17 + (jb >> 5)];
      const unsigned wd1 = sBit[r1 * 17 + (jb >> 5)];
      const int sh = (jb & 16) + 4 * tq;
      const unsigned n0 = (wd0 >> sh) & 0xFu;
      const unsigned n1 = (wd1 >> sh) & 0xFu;
      unsigned mk[4];
      mk[0] = ((n0 & 1u) ? 0x0000FFFFu : 0u) | ((n0 & 2u) ? 0xFFFF0000u : 0u);
      mk[1] = ((n1 & 1u) ? 0x0000FFFFu : 0u) | ((n1 & 2u) ? 0xFFFF0000u : 0u);
      mk[2] = ((n0 & 4u) ? 0x0000FFFFu : 0u) | ((n0 & 8u) ? 0xFFFF0000u : 0u);
      mk[3] = ((n1 & 4u) ? 0x0000FFFFu : 0u) | ((n1 & 8u) ? 0xFFFF0000u : 0u);
      const int j4 = jb + 4 * tq;

      const float4 Be = *(const float4*)(sE + (4 + h) * 400 + j4);
      const float4 De = *(const float4*)(sE + (6 + h) * 400 + j4);

      // exp(lrelu(si+sj)) = max(Ae*Be, Ce*De)
      const float p00 = fmaxf(A0 * Be.x, Q0 * De.x);
      const float p01 = fmaxf(A0 * Be.y, Q0 * De.y);
      const float p02 = fmaxf(A0 * Be.z, Q0 * De.z);
      const float p03 = fmaxf(A0 * Be.w, Q0 * De.w);
      const float p10 = fmaxf(A1 * Be.x, Q1 * De.x);
      const float p11 = fmaxf(A1 * Be.y, Q1 * De.y);
      const float p12 = fmaxf(A1 * Be.z, Q1 * De.z);
      const float p13 = fmaxf(A1 * Be.w, Q1 * De.w);

      const unsigned h0 = f16pack(p01, p00);
      const unsigned h1 = f16pack(p11, p10);
      const unsigned h2 = f16pack(p03, p02);
      const unsigned h3 = f16pack(p13, p12);
      const float2 f0 = h2f(h0), f1 = h2f(h1), f2 = h2f(h2), f3 = h2f(h3);
      unsigned ah[4], al[4];
      al[0] = f16pack(p01 - f0.y, p00 - f0.x) & mk[0];
      al[1] = f16pack(p11 - f1.y, p10 - f1.x) & mk[1];
      al[2] = f16pack(p03 - f2.y, p02 - f2.x) & mk[2];
      al[3] = f16pack(p13 - f3.y, p12 - f3.x) & mk[3];
      ah[0] = h0 & mk[0]; ah[1] = h1 & mk[1];
      ah[2] = h2 & mk[2]; ah[3] = h3 & mk[3];

      // Z via constant-ones B (fp16 1.0 = 0x3C00)
      mma16816(Cz, ah, 0x3C003C00u, 0x3C003C00u);
      mma16816(Cz, al, 0x3C003C00u, 0x3C003C00u);

#pragma unroll
      for (int nt = 0; nt < 4; ++nt) {
        const int d = h * 32 + nt * 8 + g;
        const ull bv = *(const ull*)(sm + d * 800 + 2 * j4);  // 4 fp16 V (conflict-free)
        mma16816(C[nt], ah, (unsigned)bv, (unsigned)(bv >> 32));
        mma16816(C[nt], al, (unsigned)bv, (unsigned)(bv >> 32));
      }
    }

    // normalize by Z
    const float rz0 = 1.f / Cz[0], rz1 = 1.f / Cz[2];
#pragma unroll
    for (int nt = 0; nt < 4; ++nt) {
      C[nt][0] *= rz0; C[nt][1] *= rz0;
      C[nt][2] *= rz1; C[nt][3] *= rz1;
    }

    // partial LN stats (my 32 channels), exchange with partner warp
#pragma unroll
    for (int rh = 0; rh < 2; ++rh) {
      float s = 0.f, ss = 0.f;
#pragma unroll
      for (int nt = 0; nt < 4; ++nt) {
        float o0 = C[nt][rh * 2], o1 = C[nt][rh * 2 + 1];
        s += o0 + o1; ss += o0 * o0 + o1 * o1;
      }
      s  += __shfl_xor_sync(0xffffffffu, s, 1);  s  += __shfl_xor_sync(0xffffffffu, s, 2);
      ss += __shfl_xor_sync(0xffffffffu, ss, 1); ss += __shfl_xor_sync(0xffffffffu, ss, 2);
      if (tq == 0) {
        const int row = g + 8 * rh;
        sScr[((pair * 2 + h) * 16 + row) * 2]     = s;
        sScr[((pair * 2 + h) * 16 + row) * 2 + 1] = ss;
      }
    }
    asm volatile("bar.sync %0, 64;" :: "r"(pair + 1) : "memory");
#pragma unroll
    for (int rh = 0; rh < 2; ++rh) {
      const int row = g + 8 * rh;
      float s = 0.f, ss = 0.f;
#pragma unroll
      for (int nt = 0; nt < 4; ++nt) {
        float o0 = C[nt][rh * 2], o1 = C[nt][rh * 2 + 1];
        s += o0 + o1; ss += o0 * o0 + o1 * o1;
      }
      s  += __shfl_xor_sync(0xffffffffu, s, 1);  s  += __shfl_xor_sync(0xffffffffu, s, 2);
      ss += __shfl_xor_sync(0xffffffffu, ss, 1); ss += __shfl_xor_sync(0xffffffffu, ss, 2);
      s  += sScr[((pair * 2 + (1 - h)) * 16 + row) * 2];
      ss += sScr[((pair * 2 + (1 - h)) * 16 + row) * 2 + 1];
      const float mu = s * (1.f / 64.f);
      const float var = ss * (1.f / 64.f) - mu * mu;
      const float rs = rsqrtf(var + 1e-5f);
      const int n = i0 + row;
#pragma unroll
      for (int nt = 0; nt < 4; ++nt) {
        const int d0 = h * 32 + nt * 8 + 2 * tq;
        float o0 = (C[nt][rh * 2] - mu) * rs * sLN[d0] + sLN[64 + d0];
        float o1 = (C[nt][rh * 2 + 1] - mu) * rs * sLN[d0 + 1] + sLN[64 + d0 + 1];
        obase[(size_t)d0 * 12800 + n] = o0;
        obase[(size_t)(d0 + 1) * 12800 + n] = o1;
      }
    }
    asm volatile("bar.sync %0, 64;" :: "r"(pair + 1) : "memory");  // protect sScr reuse
  }
}

extern "C" void kernel_launch(void* const* d_in, const int* in_sizes, int n_in,
                              void* d_out, int out_size) {
  const float* x     = (const float*)d_in[0];
  const float* Wq    = (const float*)d_in[1];
  const float* Wk    = (const float*)d_in[2];
  const float* Wv    = (const float*)d_in[3];
  const float* a_src = (const float*)d_in[4];
  const float* a_dst = (const float*)d_in[5];
  const float* ln_g  = (const float*)d_in[6];
  const float* ln_b  = (const float*)d_in[7];
  const int*   gso   = (const int*)d_in[8];
  float* out = (float*)d_out;

  cudaFuncSetAttribute(gat_stage, cudaFuncAttributeMaxDynamicSharedMemorySize, K1_BYTES);
  cudaFuncSetAttribute(gat_attn,  cudaFuncAttributeMaxDynamicSharedMemorySize, K2_BYTES);
  gat_prep<<<52, 256>>>(Wq, Wk, a_src, a_dst, gso);
  gat_stage<<<256, 800, K1_BYTES>>>(x, Wv);
  gat_attn<<<256, 512, K2_BYTES>>>(ln_g, ln_b, out);
}